// round 1
// baseline (speedup 1.0000x reference)
#include <cuda_runtime.h>

// ============================================================================
// StandardSelfAttention: out = Attn(x) with
//   Q/K/V = x@W* + b*  (head-split), scores = QK^T/8 + pos_bias, causal mask,
//   softmax, ctx = P@V, out = ctx@Wo + bo
// Shapes: B=2, S=2048, D=1024, H=16, Dh=64.
// Round 0: fp32 baseline. SGEMM 128x128x8 register-blocked; flash-style
// attention with streaming softmax (Q,O in regs; K,V,bias+scores in smem).
// ============================================================================

#define D_MODEL 1024
#define N_HEADS 16
#define D_HEAD 64
#define SEQ 2048
#define BATCH 2
#define M_ROWS (BATCH * SEQ)     // 4096
#define BH (BATCH * N_HEADS)     // 32

// Scratch (allocation-free contract: __device__ globals)
__device__ float g_Q[BH * SEQ * D_HEAD];
__device__ float g_K[BH * SEQ * D_HEAD];
__device__ float g_V[BH * SEQ * D_HEAD];
__device__ float g_ctx[M_ROWS * D_MODEL];

// ----------------------------------------------------------------------------
// SGEMM: C = A[M,K] @ W[K,N] + bias[N]
// mode 0: write to head-split layout [b,h,s,dh];  mode 1: plain [m,n]
// BM=BN=128, BK=8, 256 threads, 8x8 per-thread tile.
// ----------------------------------------------------------------------------
constexpr int BM = 128, BN = 128, BKK = 8;

__global__ __launch_bounds__(256) void sgemm_bias(
    const float* __restrict__ A, const float* __restrict__ W,
    const float* __restrict__ bias, float* __restrict__ C, int mode)
{
    __shared__ float As[BKK][BM];   // transposed A tile
    __shared__ float Bs[BKK][BN];
    const int K = 1024, N = 1024;

    int tid = threadIdx.x;
    int bm = blockIdx.y * BM;
    int bn = blockIdx.x * BN;

    int arow = tid >> 1;            // 0..127
    int acol = (tid & 1) * 4;       // 0 or 4
    int brow = tid >> 5;            // 0..7
    int bcol = (tid & 31) * 4;      // 0..124

    int ty = tid >> 4, tx = tid & 15;
    int rm = ty * 8, rn = tx * 8;

    float acc[8][8];
    #pragma unroll
    for (int i = 0; i < 8; i++)
        #pragma unroll
        for (int j = 0; j < 8; j++) acc[i][j] = 0.0f;

    const float* Aptr = A + (size_t)(bm + arow) * K + acol;
    const float* Wptr = W + (size_t)brow * N + bn + bcol;

    for (int k0 = 0; k0 < K; k0 += BKK) {
        float4 av = *(const float4*)(Aptr + k0);
        float4 bv = *(const float4*)(Wptr + (size_t)k0 * N);
        __syncthreads();
        As[acol + 0][arow] = av.x;
        As[acol + 1][arow] = av.y;
        As[acol + 2][arow] = av.z;
        As[acol + 3][arow] = av.w;
        *(float4*)&Bs[brow][bcol] = bv;
        __syncthreads();

        #pragma unroll
        for (int kk = 0; kk < BKK; kk++) {
            float4 a0 = *(const float4*)&As[kk][rm];
            float4 a1 = *(const float4*)&As[kk][rm + 4];
            float4 b0 = *(const float4*)&Bs[kk][rn];
            float4 b1 = *(const float4*)&Bs[kk][rn + 4];
            float ar[8] = {a0.x, a0.y, a0.z, a0.w, a1.x, a1.y, a1.z, a1.w};
            float br[8] = {b0.x, b0.y, b0.z, b0.w, b1.x, b1.y, b1.z, b1.w};
            #pragma unroll
            for (int i = 0; i < 8; i++)
                #pragma unroll
                for (int j = 0; j < 8; j++)
                    acc[i][j] += ar[i] * br[j];
        }
    }

    #pragma unroll
    for (int i = 0; i < 8; i++) {
        int m = bm + rm + i;
        #pragma unroll
        for (int j = 0; j < 8; j++) {
            int n = bn + rn + j;
            float val = acc[i][j] + bias[n];
            if (mode == 0) {
                int b = m >> 11, s = m & 2047;
                int h = n >> 6, dh = n & 63;
                C[(((size_t)(b * N_HEADS + h)) * SEQ + s) * D_HEAD + dh] = val;
            } else {
                C[(size_t)m * 1024 + n] = val;
            }
        }
    }
}

// ----------------------------------------------------------------------------
// Flash attention, fp32. Grid (S/BQ, BH). 128 threads; thread t owns q-row
// q0+t. Q row + O accumulator live in registers. K/V tiles (32x64) and the
// bias/scores tile (128x33, padded) in smem. Streaming softmax per 32-k tile.
// Writes ctx directly into [b, s, h*64+dh] layout for the output GEMM.
// ----------------------------------------------------------------------------
constexpr int BQ = 128, BKT = 32;

__global__ __launch_bounds__(128) void flash_attn(
    const float* __restrict__ Q, const float* __restrict__ K,
    const float* __restrict__ V, const float* __restrict__ pos_bias,
    float* __restrict__ ctx)
{
    __shared__ float Ks[BKT][D_HEAD];
    __shared__ float Vs[BKT][D_HEAD];
    __shared__ float Ss[BQ][BKT + 1];   // bias in, scores out (padded)

    int bh = blockIdx.y;
    int b  = bh >> 4;
    int h  = bh & 15;
    int q0 = blockIdx.x * BQ;
    int t  = threadIdx.x;
    int i  = q0 + t;                    // global query row

    // Load Q row into registers
    float q[D_HEAD];
    {
        const float4* q4 = (const float4*)(Q + ((size_t)bh * SEQ + i) * D_HEAD);
        #pragma unroll
        for (int dd = 0; dd < 16; dd++) {
            float4 v = q4[dd];
            q[dd * 4 + 0] = v.x; q[dd * 4 + 1] = v.y;
            q[dd * 4 + 2] = v.z; q[dd * 4 + 3] = v.w;
        }
    }

    float o[D_HEAD];
    #pragma unroll
    for (int d = 0; d < D_HEAD; d++) o[d] = 0.0f;
    float mrun = -3.0e38f, lrun = 0.0f;
    const float scale = 0.125f;         // 1/sqrt(64)

    const int kend = q0 + BQ;           // causal: need k < q0+BQ
    const float* pb_base = pos_bias + (size_t)h * SEQ * SEQ;

    for (int k0 = 0; k0 < kend; k0 += BKT) {
        __syncthreads();  // previous iter consumers done
        // Load K/V tiles (32x64 each), coalesced float4
        for (int idx = t; idx < BKT * D_HEAD / 4; idx += BQ) {
            int r = idx >> 4;
            int c = (idx & 15) << 2;
            *(float4*)&Ks[r][c] =
                *(const float4*)&K[((size_t)bh * SEQ + k0 + r) * D_HEAD + c];
            *(float4*)&Vs[r][c] =
                *(const float4*)&V[((size_t)bh * SEQ + k0 + r) * D_HEAD + c];
        }
        // Load bias tile [128 x 32], coalesced rows
        for (int idx = t; idx < BQ * BKT / 4; idx += BQ) {
            int r = idx >> 3;
            int c = (idx & 7) << 2;
            float4 bv = *(const float4*)&pb_base[(size_t)(q0 + r) * SEQ + k0 + c];
            Ss[r][c + 0] = bv.x; Ss[r][c + 1] = bv.y;
            Ss[r][c + 2] = bv.z; Ss[r][c + 3] = bv.w;
        }
        __syncthreads();

        // Phase 1: scores into own smem row (thread-private row => no hazard)
        for (int j = 0; j < BKT; j++) {
            float a0 = 0.f, a1 = 0.f, a2 = 0.f, a3 = 0.f;
            const float4* k4 = (const float4*)Ks[j];
            #pragma unroll
            for (int dd = 0; dd < 16; dd++) {
                float4 kv = k4[dd];
                a0 += q[dd * 4 + 0] * kv.x;
                a1 += q[dd * 4 + 1] * kv.y;
                a2 += q[dd * 4 + 2] * kv.z;
                a3 += q[dd * 4 + 3] * kv.w;
            }
            float s = (a0 + a1) + (a2 + a3);
            s = s * scale + Ss[t][j];
            s = ((k0 + j) <= i) ? s : -1.0e30f;
            Ss[t][j] = s;
        }

        // Phase 2: streaming softmax update for this tile
        float mt = -1.0e30f;
        #pragma unroll 8
        for (int j = 0; j < BKT; j++) mt = fmaxf(mt, Ss[t][j]);
        float mnew = fmaxf(mrun, mt);
        float corr = __expf(mrun - mnew);
        lrun *= corr;
        #pragma unroll
        for (int d = 0; d < D_HEAD; d++) o[d] *= corr;
        mrun = mnew;

        for (int j = 0; j < BKT; j++) {
            float p = __expf(Ss[t][j] - mnew);
            lrun += p;
            const float4* v4 = (const float4*)Vs[j];
            #pragma unroll
            for (int dd = 0; dd < 16; dd++) {
                float4 vv = v4[dd];
                o[dd * 4 + 0] += p * vv.x;
                o[dd * 4 + 1] += p * vv.y;
                o[dd * 4 + 2] += p * vv.z;
                o[dd * 4 + 3] += p * vv.w;
            }
        }
    }

    // Epilogue: normalize, write ctx[b, s=i, h*64+dh]
    float inv = 1.0f / lrun;
    float* orow = ctx + ((size_t)(b * SEQ + i)) * D_MODEL + h * D_HEAD;
    #pragma unroll
    for (int dd = 0; dd < 16; dd++) {
        float4 v;
        v.x = o[dd * 4 + 0] * inv; v.y = o[dd * 4 + 1] * inv;
        v.z = o[dd * 4 + 2] * inv; v.w = o[dd * 4 + 3] * inv;
        *(float4*)&orow[dd * 4] = v;
    }
}

// ----------------------------------------------------------------------------
// Launch
// Inputs (metadata order): 0:x 1:mask 2:Wq 3:bq 4:Wk 5:bk 6:Wv 7:bv 8:Wo 9:bo
//                          10:pos_bias
// ----------------------------------------------------------------------------
extern "C" void kernel_launch(void* const* d_in, const int* in_sizes, int n_in,
                              void* d_out, int out_size)
{
    const float* x  = (const float*)d_in[0];
    const float* Wq = (const float*)d_in[2];
    const float* bq = (const float*)d_in[3];
    const float* Wk = (const float*)d_in[4];
    const float* bk = (const float*)d_in[5];
    const float* Wv = (const float*)d_in[6];
    const float* bv = (const float*)d_in[7];
    const float* Wo = (const float*)d_in[8];
    const float* bo = (const float*)d_in[9];
    const float* pb = (const float*)d_in[10];
    float* out = (float*)d_out;

    float *qp, *kp, *vp, *cp;
    cudaGetSymbolAddress((void**)&qp, g_Q);
    cudaGetSymbolAddress((void**)&kp, g_K);
    cudaGetSymbolAddress((void**)&vp, g_V);
    cudaGetSymbolAddress((void**)&cp, g_ctx);

    dim3 ggrid(1024 / BN, M_ROWS / BM);   // (8, 32)
    sgemm_bias<<<ggrid, 256>>>(x, Wq, bq, qp, 0);
    sgemm_bias<<<ggrid, 256>>>(x, Wk, bk, kp, 0);
    sgemm_bias<<<ggrid, 256>>>(x, Wv, bv, vp, 0);

    dim3 fgrid(SEQ / BQ, BH);             // (16, 32)
    flash_attn<<<fgrid, 128>>>(qp, kp, vp, pb, cp);

    sgemm_bias<<<ggrid, 256>>>(cp, Wo, bo, out, 1);
}

// round 2
// speedup vs baseline: 3.5387x; 3.5387x over previous
#include <cuda_runtime.h>
#include <cstdint>

// ============================================================================
// StandardSelfAttention, TF32 tensor-core version (mma.sync.m16n8k8).
//   - 4 GEMMs (QKV proj + out proj): 128x128x32 tiles, 8 warps, tf32 mma.
//   - Flash attention: 64-q-row blocks, S=Q@K^T and O=P@V via tf32 mma,
//     streaming softmax on fragments, P via warp-private smem round trip.
//   - All tf32 conversions use cvt.rna (round-to-nearest) to avoid the
//     systematic truncation bias. Q is pre-scaled by 1/8 (exact pow2).
// Shapes: B=2, S=2048, D=1024, H=16, Dh=64.
// ============================================================================

#define D_MODEL 1024
#define N_HEADS 16
#define D_HEAD 64
#define SEQ 2048
#define BATCH 2
#define M_ROWS (BATCH * SEQ)     // 4096
#define BH (BATCH * N_HEADS)     // 32

// Scratch (allocation-free contract: __device__ globals)
__device__ float g_Q[BH * SEQ * D_HEAD];
__device__ float g_K[BH * SEQ * D_HEAD];
__device__ float g_V[BH * SEQ * D_HEAD];
__device__ float g_ctx[M_ROWS * D_MODEL];

__device__ __forceinline__ uint32_t f2tf(float x) {
    uint32_t r;
    asm("cvt.rna.tf32.f32 %0, %1;" : "=r"(r) : "f"(x));
    return r;
}

__device__ __forceinline__ void mma_tf32(float* c,
    uint32_t a0, uint32_t a1, uint32_t a2, uint32_t a3,
    uint32_t b0, uint32_t b1)
{
    asm volatile(
        "mma.sync.aligned.m16n8k8.row.col.f32.tf32.tf32.f32 "
        "{%0,%1,%2,%3}, {%4,%5,%6,%7}, {%8,%9}, {%0,%1,%2,%3};\n"
        : "+f"(c[0]), "+f"(c[1]), "+f"(c[2]), "+f"(c[3])
        : "r"(a0), "r"(a1), "r"(a2), "r"(a3), "r"(b0), "r"(b1));
}

// ----------------------------------------------------------------------------
// TF32 GEMM: C = A[M,1024] @ W[1024,1024] + bias
// mode 0: head-split output [b,h,s,dh], cvt.rna + scale applied (feeds attn)
// mode 1: plain [m,n] fp32 output
// BM=BN=128, BK=32, 256 threads (8 warps, 2x4), per-warp 64x32 via 4x4 mma tiles
// ----------------------------------------------------------------------------
constexpr int AST = 36;    // A smem stride (floats)  (36%32=4 -> conflict-free frags)
constexpr int BST = 136;   // B smem stride           (136%32=8 -> conflict-free frags)

__global__ __launch_bounds__(256) void gemm_tf32(
    const float* __restrict__ A, const float* __restrict__ W,
    const float* __restrict__ bias, float* __restrict__ C,
    int mode, float scale)
{
    __shared__ uint32_t As[128 * AST];
    __shared__ uint32_t Bs[32 * BST];

    int tid = threadIdx.x;
    int lane = tid & 31, wid = tid >> 5;
    int wm = wid >> 2, wn = wid & 3;
    int bm = blockIdx.y * 128, bn = blockIdx.x * 128;
    int r = lane >> 2, cc4 = lane & 3;

    // global load mapping
    int arow = tid >> 1;            // 0..127
    int acol = (tid & 1) * 16;      // 0/16
    int brow = tid >> 3;            // 0..31
    int bcol = (tid & 7) * 4;       // 0..28, +i*32

    const float* Ap = A + (size_t)(bm + arow) * 1024 + acol;
    const float* Wp = W + (size_t)brow * 1024 + bn + bcol;

    float acc[4][4][4];
    #pragma unroll
    for (int mt = 0; mt < 4; mt++)
        #pragma unroll
        for (int nt = 0; nt < 4; nt++)
            #pragma unroll
            for (int i = 0; i < 4; i++) acc[mt][nt][i] = 0.0f;

    // prefetch tile 0
    float4 areg[4], breg[4];
    #pragma unroll
    for (int i = 0; i < 4; i++) {
        areg[i] = *(const float4*)(Ap + i * 4);
        breg[i] = *(const float4*)(Wp + (size_t)i * 32);
    }

    for (int k0 = 0; k0 < 1024; k0 += 32) {
        // store current tile (cvt.rna to tf32 bits)
        #pragma unroll
        for (int i = 0; i < 4; i++) {
            uint32_t* d = &As[arow * AST + acol + i * 4];
            d[0] = f2tf(areg[i].x); d[1] = f2tf(areg[i].y);
            d[2] = f2tf(areg[i].z); d[3] = f2tf(areg[i].w);
            uint32_t* e = &Bs[brow * BST + bcol + i * 32];
            e[0] = f2tf(breg[i].x); e[1] = f2tf(breg[i].y);
            e[2] = f2tf(breg[i].z); e[3] = f2tf(breg[i].w);
        }
        __syncthreads();

        // prefetch next tile
        if (k0 + 32 < 1024) {
            #pragma unroll
            for (int i = 0; i < 4; i++) {
                areg[i] = *(const float4*)(Ap + k0 + 32 + i * 4);
                breg[i] = *(const float4*)(Wp + (size_t)(k0 + 32) * 1024 + (size_t)i * 32);
            }
        }

        // compute
        #pragma unroll
        for (int ks = 0; ks < 4; ks++) {
            int k = ks * 8;
            uint32_t af[4][4];
            #pragma unroll
            for (int mt = 0; mt < 4; mt++) {
                const uint32_t* ab = &As[(wm * 64 + mt * 16 + r) * AST + k + cc4];
                af[mt][0] = ab[0];
                af[mt][1] = ab[8 * AST];
                af[mt][2] = ab[4];
                af[mt][3] = ab[8 * AST + 4];
            }
            #pragma unroll
            for (int nt = 0; nt < 4; nt++) {
                const uint32_t* bb = &Bs[(k + cc4) * BST + wn * 32 + nt * 8 + r];
                uint32_t b0 = bb[0], b1 = bb[4 * BST];
                #pragma unroll
                for (int mt = 0; mt < 4; mt++)
                    mma_tf32(acc[mt][nt], af[mt][0], af[mt][1], af[mt][2], af[mt][3], b0, b1);
            }
        }
        __syncthreads();
    }

    // epilogue
    #pragma unroll
    for (int mt = 0; mt < 4; mt++) {
        int r0 = bm + wm * 64 + mt * 16 + r;
        #pragma unroll
        for (int nt = 0; nt < 4; nt++) {
            int col = bn + wn * 32 + nt * 8 + 2 * cc4;
            float bz0 = bias[col], bz1 = bias[col + 1];
            #pragma unroll
            for (int half = 0; half < 2; half++) {
                int m = r0 + half * 8;
                float v0 = acc[mt][nt][half * 2 + 0] + bz0;
                float v1 = acc[mt][nt][half * 2 + 1] + bz1;
                if (mode == 0) {
                    // cvt.rna so attention can consume exact tf32 values
                    v0 = __uint_as_float(f2tf(v0 * scale));
                    v1 = __uint_as_float(f2tf(v1 * scale));
                    int b = m >> 11, s = m & 2047;
                    int h = col >> 6, dh = col & 63;
                    float2* dst = (float2*)&C[(((size_t)(b * N_HEADS + h)) * SEQ + s) * D_HEAD + dh];
                    *dst = make_float2(v0, v1);
                } else {
                    *(float2*)&C[(size_t)m * 1024 + col] = make_float2(v0, v1);
                }
            }
        }
    }
}

// ----------------------------------------------------------------------------
// Flash attention with tf32 mma. Block = 64 q-rows of one (b,h). 4 warps,
// each warp owns 16 q-rows. K/V tiles of 64 keys. Scores + bias + causal +
// streaming softmax entirely on mma fragments; P through warp-private smem.
// Writes ctx in [b, s, h*64+dh] layout (fp32).
// ----------------------------------------------------------------------------
constexpr int QST = 68;   // 68%32=4
constexpr int KST = 68;
constexpr int VST = 72;   // 72%32=8
constexpr int PST = 68;
constexpr int ATTN_SMEM = (64 * QST + 64 * KST + 64 * VST + 64 * PST) * 4;  // 70656 B

__global__ __launch_bounds__(128) void attn_mma(
    const float* __restrict__ Q, const float* __restrict__ K,
    const float* __restrict__ V, const float* __restrict__ pb,
    float* __restrict__ ctx)
{
    extern __shared__ uint32_t sm[];
    uint32_t* Qs = sm;                 // [64][QST]
    uint32_t* Ks = Qs + 64 * QST;      // [64][KST]
    uint32_t* Vs = Ks + 64 * KST;      // [64][VST]
    uint32_t* Ps = Vs + 64 * VST;      // 4 warps x [16][PST]

    int tid = threadIdx.x, lane = tid & 31, w = tid >> 5;
    int r = lane >> 2, c = lane & 3;
    int bh = blockIdx.y, b = bh >> 4, h = bh & 15;
    int q0 = blockIdx.x * 64;

    // load Q tile (already tf32-valued f32; reinterpret bits)
    const float* Qg = Q + ((size_t)bh * SEQ + q0) * D_HEAD;
    for (int i = tid; i < 64 * 16; i += 128) {
        int rr = i >> 4, ccc = (i & 15) << 2;
        float4 v = *(const float4*)(Qg + (size_t)rr * D_HEAD + ccc);
        uint32_t* d = &Qs[rr * QST + ccc];
        d[0] = __float_as_uint(v.x); d[1] = __float_as_uint(v.y);
        d[2] = __float_as_uint(v.z); d[3] = __float_as_uint(v.w);
    }

    float oacc[8][4];
    #pragma unroll
    for (int nt = 0; nt < 8; nt++)
        #pragma unroll
        for (int i = 0; i < 4; i++) oacc[nt][i] = 0.0f;

    float m0 = -1e30f, m1 = -1e30f, l0 = 0.0f, l1 = 0.0f;

    const float* Kg = K + (size_t)bh * SEQ * D_HEAD;
    const float* Vg = V + (size_t)bh * SEQ * D_HEAD;
    const float* pbase = pb + (size_t)h * SEQ * SEQ;
    int qrow = q0 + w * 16 + r;
    uint32_t* Pw = Ps + w * 16 * PST;

    for (int k0 = 0; k0 <= q0; k0 += 64) {
        __syncthreads();
        // load K/V tiles
        for (int i = tid; i < 64 * 16; i += 128) {
            int rr = i >> 4, ccc = (i & 15) << 2;
            float4 kv = *(const float4*)(Kg + (size_t)(k0 + rr) * D_HEAD + ccc);
            float4 vv = *(const float4*)(Vg + (size_t)(k0 + rr) * D_HEAD + ccc);
            uint32_t* dk = &Ks[rr * KST + ccc];
            dk[0] = __float_as_uint(kv.x); dk[1] = __float_as_uint(kv.y);
            dk[2] = __float_as_uint(kv.z); dk[3] = __float_as_uint(kv.w);
            uint32_t* dv = &Vs[rr * VST + ccc];
            dv[0] = __float_as_uint(vv.x); dv[1] = __float_as_uint(vv.y);
            dv[2] = __float_as_uint(vv.z); dv[3] = __float_as_uint(vv.w);
        }
        __syncthreads();

        // S = Q @ K^T  (scale already folded into Q)
        float sacc[8][4];
        #pragma unroll
        for (int nt = 0; nt < 8; nt++)
            #pragma unroll
            for (int i = 0; i < 4; i++) sacc[nt][i] = 0.0f;

        #pragma unroll
        for (int ks = 0; ks < 8; ks++) {
            int kk = ks * 8;
            const uint32_t* ab = &Qs[(w * 16 + r) * QST + kk + c];
            uint32_t a0 = ab[0], a1 = ab[8 * QST], a2 = ab[4], a3 = ab[8 * QST + 4];
            #pragma unroll
            for (int nt = 0; nt < 8; nt++) {
                const uint32_t* bb = &Ks[(nt * 8 + r) * KST + kk + c];
                mma_tf32(sacc[nt], a0, a1, a2, a3, bb[0], bb[4]);
            }
        }

        // + bias, causal mask on diagonal tile
        bool diag = (k0 == q0);
        #pragma unroll
        for (int nt = 0; nt < 8; nt++) {
            int col = k0 + nt * 8 + 2 * c;
            float2 bz0 = *(const float2*)(pbase + (size_t)qrow * SEQ + col);
            float2 bz1 = *(const float2*)(pbase + (size_t)(qrow + 8) * SEQ + col);
            sacc[nt][0] += bz0.x; sacc[nt][1] += bz0.y;
            sacc[nt][2] += bz1.x; sacc[nt][3] += bz1.y;
            if (diag) {
                if (col > qrow)         sacc[nt][0] = -1e30f;
                if (col + 1 > qrow)     sacc[nt][1] = -1e30f;
                if (col > qrow + 8)     sacc[nt][2] = -1e30f;
                if (col + 1 > qrow + 8) sacc[nt][3] = -1e30f;
            }
        }

        // streaming softmax: row max (4 lanes share a row)
        float t0 = -1e30f, t1 = -1e30f;
        #pragma unroll
        for (int nt = 0; nt < 8; nt++) {
            t0 = fmaxf(t0, fmaxf(sacc[nt][0], sacc[nt][1]));
            t1 = fmaxf(t1, fmaxf(sacc[nt][2], sacc[nt][3]));
        }
        t0 = fmaxf(t0, __shfl_xor_sync(0xffffffffu, t0, 1));
        t0 = fmaxf(t0, __shfl_xor_sync(0xffffffffu, t0, 2));
        t1 = fmaxf(t1, __shfl_xor_sync(0xffffffffu, t1, 1));
        t1 = fmaxf(t1, __shfl_xor_sync(0xffffffffu, t1, 2));

        float mn0 = fmaxf(m0, t0), mn1 = fmaxf(m1, t1);
        float cor0 = __expf(m0 - mn0), cor1 = __expf(m1 - mn1);
        m0 = mn0; m1 = mn1;
        l0 *= cor0; l1 *= cor1;

        // exp, partial row sums, write P to warp-private smem (tf32 bits)
        __syncwarp();
        float ps0 = 0.0f, ps1 = 0.0f;
        #pragma unroll
        for (int nt = 0; nt < 8; nt++) {
            float p00 = __expf(sacc[nt][0] - mn0);
            float p01 = __expf(sacc[nt][1] - mn0);
            float p10 = __expf(sacc[nt][2] - mn1);
            float p11 = __expf(sacc[nt][3] - mn1);
            ps0 += p00 + p01; ps1 += p10 + p11;
            *(uint2*)&Pw[r * PST + nt * 8 + 2 * c] = make_uint2(f2tf(p00), f2tf(p01));
            *(uint2*)&Pw[(r + 8) * PST + nt * 8 + 2 * c] = make_uint2(f2tf(p10), f2tf(p11));
        }
        ps0 += __shfl_xor_sync(0xffffffffu, ps0, 1);
        ps0 += __shfl_xor_sync(0xffffffffu, ps0, 2);
        ps1 += __shfl_xor_sync(0xffffffffu, ps1, 1);
        ps1 += __shfl_xor_sync(0xffffffffu, ps1, 2);
        l0 += ps0; l1 += ps1;

        // rescale O
        #pragma unroll
        for (int nt = 0; nt < 8; nt++) {
            oacc[nt][0] *= cor0; oacc[nt][1] *= cor0;
            oacc[nt][2] *= cor1; oacc[nt][3] *= cor1;
        }
        __syncwarp();

        // O += P @ V
        #pragma unroll
        for (int ks = 0; ks < 8; ks++) {
            int kk = ks * 8;
            const uint32_t* ab = &Pw[r * PST + kk + c];
            uint32_t a0 = ab[0], a1 = ab[8 * PST], a2 = ab[4], a3 = ab[8 * PST + 4];
            #pragma unroll
            for (int nt = 0; nt < 8; nt++) {
                const uint32_t* bb = &Vs[(kk + c) * VST + nt * 8 + r];
                mma_tf32(oacc[nt], a0, a1, a2, a3, bb[0], bb[4 * VST]);
            }
        }
    }

    // epilogue: normalize, write ctx[b, q, h*64+d]
    float inv0 = 1.0f / l0, inv1 = 1.0f / l1;
    float* cb = ctx + ((size_t)(b * SEQ + qrow)) * D_MODEL + h * D_HEAD;
    #pragma unroll
    for (int nt = 0; nt < 8; nt++) {
        *(float2*)(cb + nt * 8 + 2 * c) =
            make_float2(oacc[nt][0] * inv0, oacc[nt][1] * inv0);
        *(float2*)(cb + (size_t)8 * D_MODEL + nt * 8 + 2 * c) =
            make_float2(oacc[nt][2] * inv1, oacc[nt][3] * inv1);
    }
}

// ----------------------------------------------------------------------------
// Launch. Inputs: 0:x 1:mask 2:Wq 3:bq 4:Wk 5:bk 6:Wv 7:bv 8:Wo 9:bo 10:pos_bias
// ----------------------------------------------------------------------------
extern "C" void kernel_launch(void* const* d_in, const int* in_sizes, int n_in,
                              void* d_out, int out_size)
{
    const float* x  = (const float*)d_in[0];
    const float* Wq = (const float*)d_in[2];
    const float* bq = (const float*)d_in[3];
    const float* Wk = (const float*)d_in[4];
    const float* bk = (const float*)d_in[5];
    const float* Wv = (const float*)d_in[6];
    const float* bv = (const float*)d_in[7];
    const float* Wo = (const float*)d_in[8];
    const float* bo = (const float*)d_in[9];
    const float* pb = (const float*)d_in[10];
    float* out = (float*)d_out;

    float *qp, *kp, *vp, *cp;
    cudaGetSymbolAddress((void**)&qp, g_Q);
    cudaGetSymbolAddress((void**)&kp, g_K);
    cudaGetSymbolAddress((void**)&vp, g_V);
    cudaGetSymbolAddress((void**)&cp, g_ctx);

    static bool attr_done = false;
    if (!attr_done) {
        cudaFuncSetAttribute(attn_mma, cudaFuncAttributeMaxDynamicSharedMemorySize,
                             ATTN_SMEM);
        attr_done = true;
    }

    dim3 ggrid(8, 32);  // N/128, M/128
    gemm_tf32<<<ggrid, 256>>>(x, Wq, bq, qp, 0, 0.125f);  // scale folded into Q
    gemm_tf32<<<ggrid, 256>>>(x, Wk, bk, kp, 0, 1.0f);
    gemm_tf32<<<ggrid, 256>>>(x, Wv, bv, vp, 0, 1.0f);

    dim3 agrid(SEQ / 64, BH);  // (32, 32)
    attn_mma<<<agrid, 128, ATTN_SMEM>>>(qp, kp, vp, pb, cp);

    gemm_tf32<<<ggrid, 256>>>(cp, Wo, bo, out, 1, 1.0f);
}